// round 9
// baseline (speedup 1.0000x reference)
#include <cuda_runtime.h>
#include <stdint.h>

#define NUM_GRAPHS 4096
#define EMB_DIM 128
#define THREADS 128
#define CHUNK 32                         // rows per stage
#define STAGE_FLOATS (CHUNK * EMB_DIM)   // 4096 floats = 16 KB

__device__ __forceinline__ uint32_t smem_u32(const void* p)
{
    uint32_t a;
    asm("{ .reg .u64 tmp; cvta.to.shared.u64 tmp, %1; cvt.u32.u64 %0, tmp; }"
        : "=r"(a) : "l"(p));
    return a;
}

__device__ __forceinline__ void mbar_wait(uint32_t mbar, uint32_t parity)
{
    asm volatile(
        "{\n\t"
        ".reg .pred P;\n\t"
        "W:\n\t"
        "mbarrier.try_wait.parity.acquire.cta.shared::cta.b64 P, [%0], %1, 0x989680;\n\t"
        "@P bra D;\n\t"
        "bra W;\n\t"
        "D:\n\t"
        "}"
        :: "r"(mbar), "r"(parity) : "memory");
}

__global__ __launch_bounds__(THREADS)
void att_pool_kernel(const float* __restrict__ x,
                     const void* __restrict__ batch_raw,
                     const float* __restrict__ w,
                     float* __restrict__ out,
                     int n_nodes, int out_size)
{
    const int t    = threadIdx.x;
    const int g    = blockIdx.x;
    const int warp = t >> 5;
    const int lane = t & 31;

    __shared__ alignas(128) float stage[2][STAGE_FLOATS];  // 32 KB
    __shared__ float es[CHUNK];
    __shared__ float ls[4];
    __shared__ alignas(8) uint64_t mbar[2];
    __shared__ int s_start, s_end;

    // Binary search contiguous [start,end) for graph g (batch sorted).
    // dtype probe: int32 -> word n-1 is the last graph id (!=0);
    // int64 (values < 2^31, LE) -> word n-1 is an upper half (==0).
    if (t == 0) {
        const int*       b32 = (const int*)batch_raw;
        const long long* b64 = (const long long*)batch_raw;
        const bool is64 = (b32[n_nodes - 1] == 0);

        long long gv = (long long)g;
        int lo = 0, hi = n_nodes;
        while (lo < hi) {
            int mid = (lo + hi) >> 1;
            long long v = is64 ? b64[mid] : (long long)b32[mid];
            if (v < gv) lo = mid + 1; else hi = mid;
        }
        s_start = lo;
        hi = n_nodes;
        const long long gv1 = gv + 1;
        while (lo < hi) {
            int mid = (lo + hi) >> 1;
            long long v = is64 ? b64[mid] : (long long)b32[mid];
            if (v < gv1) lo = mid + 1; else hi = mid;
        }
        s_end = lo;

        // init mbarriers + prologue TMA bulk loads for chunks 0,1
        const uint32_t mb0 = smem_u32(&mbar[0]);
        const uint32_t mb1 = smem_u32(&mbar[1]);
        asm volatile("mbarrier.init.shared.b64 [%0], 1;" :: "r"(mb0) : "memory");
        asm volatile("mbarrier.init.shared.b64 [%0], 1;" :: "r"(mb1) : "memory");

        const int start = lo - (lo - s_start);  // = s_start
        const int cnt = s_end - s_start;
        const int nchunks = (cnt + CHUNK - 1) / CHUNK;
        for (int c = 0; c < 2 && c < nchunks; c++) {
            const int c0   = s_start + c * CHUNK;
            const int clen = min(CHUNK, s_end - c0);
            const int bytes = clen * EMB_DIM * 4;
            const uint32_t mb = c ? mb1 : mb0;
            const uint32_t dst = smem_u32(&stage[c][0]);
            const float* src = x + (size_t)c0 * EMB_DIM;
            asm volatile("mbarrier.arrive.expect_tx.shared.b64 _, [%0], %1;"
                         :: "r"(mb), "r"(bytes) : "memory");
            asm volatile("cp.async.bulk.shared::cta.global.mbarrier::complete_tx::bytes "
                         "[%0], [%1], %2, [%3];"
                         :: "r"(dst), "l"(src), "r"(bytes), "r"(mb) : "memory");
        }
        (void)start;
    }

    const float4 wv = ((const float4*)w)[lane];
    __syncthreads();

    const int start = s_start;
    const int end   = s_end;
    const int cnt   = end - start;
    const int nchunks = (cnt + CHUNK - 1) / CHUNK;

    const uint32_t mba[2] = { smem_u32(&mbar[0]), smem_u32(&mbar[1]) };

    float acc = 0.f;   // thread t owns output dim t (complete, no cross-warp merge)
    float lw  = 0.f;   // per-warp partial denominator (valid on lane 0)

    for (int c = 0; c < nchunks; c++) {
        const int sidx = c & 1;
        mbar_wait(mba[sidx], (c >> 1) & 1);

        const int c0   = start + c * CHUNK;
        const int clen = min(CHUNK, end - c0);
        const float* sf = stage[sidx];

        // --- score phase: warp-per-row float4 dot + butterfly; es[j] = exp ---
        for (int j = warp; j < clen; j += 4) {
            const float4 xv = ((const float4*)(sf + j * EMB_DIM))[lane];
            float p = xv.x * wv.x + xv.y * wv.y + xv.z * wv.z + xv.w * wv.w;
            #pragma unroll
            for (int o = 16; o; o >>= 1) p += __shfl_xor_sync(0xffffffffu, p, o);
            // no-max softmax (shift-invariant; scores small enough for fp32 exp)
            const float e = __expf(p);
            if (lane == 0) { es[j] = e; lw += e; }
        }
        __syncthreads();   // es ready

        // --- accumulate phase: thread t sums es[j]*x[j][t]; two chains for ILP ---
        float a0 = 0.f, a1 = 0.f;
        int j = 0;
        for (; j + 1 < clen; j += 2) {
            a0 += es[j]     * sf[j * EMB_DIM + t];
            a1 += es[j + 1] * sf[(j + 1) * EMB_DIM + t];
        }
        if (j < clen) a0 += es[j] * sf[j * EMB_DIM + t];
        acc += a0 + a1;
        __syncthreads();   // stage fully consumed before refill

        // --- refill this stage with chunk c+2 ---
        const int cn = c + 2;
        if (t == 0 && cn < nchunks) {
            const int cc0  = start + cn * CHUNK;
            const int cl   = min(CHUNK, end - cc0);
            const int bytes = cl * EMB_DIM * 4;
            const uint32_t dst = smem_u32(&stage[sidx][0]);
            const float* src = x + (size_t)cc0 * EMB_DIM;
            asm volatile("mbarrier.arrive.expect_tx.shared.b64 _, [%0], %1;"
                         :: "r"(mba[sidx]), "r"(bytes) : "memory");
            asm volatile("cp.async.bulk.shared::cta.global.mbarrier::complete_tx::bytes "
                         "[%0], [%1], %2, [%3];"
                         :: "r"(dst), "l"(src), "r"(bytes), "r"(mba[sidx]) : "memory");
        }
    }

    // --- combine denominator across 4 warps ---
    if (lane == 0) ls[warp] = lw;
    __syncthreads();
    const float L = ls[0] + ls[1] + ls[2] + ls[3];

    const float denom = fmaxf(L, 1e-30f) * fmaxf((float)cnt, 1.0f);
    out[(size_t)g * EMB_DIM + t] = acc / denom;

    if (g == 0 && out_size >= NUM_GRAPHS * EMB_DIM + EMB_DIM) {
        out[NUM_GRAPHS * EMB_DIM + t] = w[t];
    }
}

extern "C" void kernel_launch(void* const* d_in, const int* in_sizes, int n_in,
                              void* d_out, int out_size)
{
    const float* x     = (const float*)d_in[0];
    const void*  batch = d_in[1];
    const float* w     = (const float*)d_in[2];
    float*       out   = (float*)d_out;
    const int n_nodes  = in_sizes[1];

    att_pool_kernel<<<NUM_GRAPHS, THREADS>>>(x, batch, w, out, n_nodes, out_size);
}

// round 11
// speedup vs baseline: 1.5442x; 1.5442x over previous
#include <cuda_runtime.h>
#include <stdint.h>

#define NUM_GRAPHS 4096
#define EMB_DIM    128
#define THREADS    128
#define DEPTH      6                 // per-warp cp.async ring depth (rows)
#define NBLOCKS    (152 * 16)        // GB300: one exact wave at 16 blocks/SM
#define NWARPS     (NBLOCKS * 4)

__device__ float g_acc[NUM_GRAPHS * EMB_DIM];
__device__ float g_l[NUM_GRAPHS];
__device__ float g_cnt[NUM_GRAPHS];

__global__ __launch_bounds__(512)
void zero_kernel()
{
    const int i = blockIdx.x * 512 + threadIdx.x;
    ((float4*)g_acc)[i] = make_float4(0.f, 0.f, 0.f, 0.f);   // 131072 float4
    if (i < NUM_GRAPHS) { g_l[i] = 0.f; g_cnt[i] = 0.f; }
}

__device__ __forceinline__ int gid_at(const int* b32, const long long* b64,
                                      bool is64, int i)
{
    return is64 ? (int)b64[i] : b32[i];
}

__global__ __launch_bounds__(THREADS)
void att_partial_kernel(const float* __restrict__ x,
                        const void* __restrict__ batch_raw,
                        const float* __restrict__ w,
                        int n_nodes)
{
    const int t    = threadIdx.x;
    const int warp = t >> 5;
    const int lane = t & 31;

    __shared__ float4 buf[4][DEPTH][32];   // 12 KB ring: [warp][slot][lane]

    // dtype probe: int32 -> word n-1 is the last graph id (!=0);
    // int64 (values < 2^31, LE) -> word n-1 is an upper half (==0).
    const int*       b32 = (const int*)batch_raw;
    const long long* b64 = (const long long*)batch_raw;
    const bool is64 = (b32[n_nodes - 1] == 0);

    // per-lane weight float4 (uniform across warps, L1-resident)
    const float4 wvec = ((const float4*)w)[lane];

    // perfectly balanced contiguous warp slice
    const int gw       = blockIdx.x * 4 + warp;
    const int per_warp = (n_nodes + NWARPS - 1) / NWARPS;
    const int ws       = gw * per_warp;
    const int we       = min(n_nodes, ws + per_warp);
    if (ws >= we) return;

    const uint32_t sbase = (uint32_t)__cvta_generic_to_shared(&buf[warp][0][lane]);

    int s = ws;
    int gseg = gid_at(b32, b64, is64, ws);
    const int glast = gid_at(b32, b64, is64, we - 1);

    while (s < we) {
        // segment end: we if this is the slice's last graph, else upper_bound
        int e;
        if (gseg == glast) {
            e = we;
        } else {
            int lo = s + 1, hi = we;
            while (lo < hi) {
                int mid = (lo + hi) >> 1;
                if (gid_at(b32, b64, is64, mid) <= gseg) lo = mid + 1; else hi = mid;
            }
            e = lo;
        }
        const int nrows = e - s;

        // ---- R6-style cp.async ring over contiguous rows [s, e) ----
        const float* base = x + (size_t)s * EMB_DIM + lane * 4;

        #pragma unroll
        for (int d = 0; d < DEPTH; d++) {
            if (d < nrows) {
                const float* src = base + (size_t)d * EMB_DIM;
                asm volatile("cp.async.cg.shared.global [%0], [%1], 16;\n"
                             :: "r"(sbase + d * 512), "l"(src));
            }
            asm volatile("cp.async.commit_group;\n");
        }

        float4 acc = make_float4(0.f, 0.f, 0.f, 0.f);
        float  l   = 0.f;
        int slot = 0;

        const int npairs = nrows >> 1;
        for (int ip = 0; ip < npairs; ip++) {
            const int i = ip * 2;
            asm volatile("cp.async.wait_group %0;\n" :: "n"(DEPTH - 2));
            const float4 xv0 = buf[warp][slot][lane];
            const float4 xv1 = buf[warp][slot + 1][lane];

            const int nr0 = i + DEPTH, nr1 = i + DEPTH + 1;
            if (nr0 < nrows) {
                const float* src = base + (size_t)nr0 * EMB_DIM;
                asm volatile("cp.async.cg.shared.global [%0], [%1], 16;\n"
                             :: "r"(sbase + slot * 512), "l"(src));
            }
            asm volatile("cp.async.commit_group;\n");
            if (nr1 < nrows) {
                const float* src = base + (size_t)nr1 * EMB_DIM;
                asm volatile("cp.async.cg.shared.global [%0], [%1], 16;\n"
                             :: "r"(sbase + (slot + 1) * 512), "l"(src));
            }
            asm volatile("cp.async.commit_group;\n");

            float p0 = xv0.x*wvec.x + xv0.y*wvec.y + xv0.z*wvec.z + xv0.w*wvec.w;
            float p1 = xv1.x*wvec.x + xv1.y*wvec.y + xv1.z*wvec.z + xv1.w*wvec.w;
            #pragma unroll
            for (int o = 16; o; o >>= 1) {
                p0 += __shfl_xor_sync(0xffffffffu, p0, o);
                p1 += __shfl_xor_sync(0xffffffffu, p1, o);
            }
            // no-max softmax (shift-invariant; scores small enough for fp32 exp)
            const float e0 = __expf(p0);
            const float e1 = __expf(p1);
            acc.x += e0*xv0.x; acc.y += e0*xv0.y; acc.z += e0*xv0.z; acc.w += e0*xv0.w;
            acc.x += e1*xv1.x; acc.y += e1*xv1.y; acc.z += e1*xv1.z; acc.w += e1*xv1.w;
            l += e0 + e1;

            slot += 2;
            if (slot == DEPTH) slot = 0;
        }
        if (nrows & 1) {
            asm volatile("cp.async.wait_group 0;\n");
            const float4 xv = buf[warp][slot][lane];
            float p = xv.x*wvec.x + xv.y*wvec.y + xv.z*wvec.z + xv.w*wvec.w;
            #pragma unroll
            for (int o = 16; o; o >>= 1) p += __shfl_xor_sync(0xffffffffu, p, o);
            const float e = __expf(p);
            acc.x += e*xv.x; acc.y += e*xv.y; acc.z += e*xv.z; acc.w += e*xv.w;
            l += e;
        }
        asm volatile("cp.async.wait_group 0;\n");   // drain before slot reuse

        // ---- flush segment into global partials ----
        float* dst = g_acc + (size_t)gseg * EMB_DIM + lane * 4;
        atomicAdd(dst + 0, acc.x);
        atomicAdd(dst + 1, acc.y);
        atomicAdd(dst + 2, acc.z);
        atomicAdd(dst + 3, acc.w);
        if (lane == 0) {
            atomicAdd(&g_l[gseg], l);
            atomicAdd(&g_cnt[gseg], (float)nrows);
        }

        s = e;
        if (s < we) gseg = gid_at(b32, b64, is64, s);
    }
}

__global__ __launch_bounds__(256)
void finalize_kernel(const float* __restrict__ w,
                     float* __restrict__ out, int out_size)
{
    const int i = blockIdx.x * 256 + threadIdx.x;
    if (i < NUM_GRAPHS * EMB_DIM) {
        const int g = i >> 7;
        const float denom = fmaxf(g_l[g], 1e-30f) * fmaxf(g_cnt[g], 1.0f);
        out[i] = g_acc[i] / denom;
    }
    if (i < EMB_DIM && out_size >= NUM_GRAPHS * EMB_DIM + EMB_DIM)
        out[NUM_GRAPHS * EMB_DIM + i] = w[i];
}

extern "C" void kernel_launch(void* const* d_in, const int* in_sizes, int n_in,
                              void* d_out, int out_size)
{
    const float* x     = (const float*)d_in[0];
    const void*  batch = d_in[1];
    const float* w     = (const float*)d_in[2];
    float*       out   = (float*)d_out;
    const int n_nodes  = in_sizes[1];

    zero_kernel<<<256, 512>>>();
    att_partial_kernel<<<NBLOCKS, THREADS>>>(x, batch, w, n_nodes);
    finalize_kernel<<<(NUM_GRAPHS * EMB_DIM + 255) / 256, 256>>>(w, out, out_size);
}

// round 12
// speedup vs baseline: 1.5878x; 1.0283x over previous
#include <cuda_runtime.h>
#include <stdint.h>

#define NUM_GRAPHS 4096
#define EMB_DIM    128
#define THREADS    128
#define DEPTH_P    3                 // cp.async ring depth in PAIRS (6 rows)
#define NBLOCKS    (152 * 16)        // GB300: one exact wave at 16 blocks/SM
#define NWARPS     (NBLOCKS * 4)

// zero-initialized at module load; finalize_kernel restores zeros after use,
// so the invariant holds at the start of every kernel_launch call.
__device__ float g_acc[NUM_GRAPHS * EMB_DIM];
__device__ float g_l[NUM_GRAPHS];
__device__ float g_cnt[NUM_GRAPHS];

__device__ __forceinline__ int gid_at(const int* b32, const long long* b64,
                                      bool is64, int i)
{
    return is64 ? (int)b64[i] : b32[i];
}

__global__ __launch_bounds__(THREADS)
void att_partial_kernel(const float* __restrict__ x,
                        const void* __restrict__ batch_raw,
                        const float* __restrict__ w,
                        int n_nodes)
{
    const int t    = threadIdx.x;
    const int warp = t >> 5;
    const int lane = t & 31;

    __shared__ float4 buf[4][DEPTH_P * 2][32];   // 12 KB ring: [warp][row slot][lane]

    // dtype probe: int32 -> word n-1 is the last graph id (!=0);
    // int64 (values < 2^31, LE) -> word n-1 is an upper half (==0).
    const int*       b32 = (const int*)batch_raw;
    const long long* b64 = (const long long*)batch_raw;
    const bool is64 = (b32[n_nodes - 1] == 0);

    const float4 wvec = ((const float4*)w)[lane];

    // perfectly balanced contiguous warp slice
    const int gw       = blockIdx.x * 4 + warp;
    const int per_warp = (n_nodes + NWARPS - 1) / NWARPS;
    const int ws       = gw * per_warp;
    const int we       = min(n_nodes, ws + per_warp);
    if (ws >= we) return;

    const uint32_t sbase = (uint32_t)__cvta_generic_to_shared(&buf[warp][0][lane]);

    int s = ws;
    int gseg = gid_at(b32, b64, is64, ws);
    const int glast = gid_at(b32, b64, is64, we - 1);

    while (s < we) {
        // segment end: we if this is the slice's last graph, else upper_bound
        int e;
        if (gseg == glast) {
            e = we;
        } else {
            int lo = s + 1, hi = we;
            while (lo < hi) {
                int mid = (lo + hi) >> 1;
                if (gid_at(b32, b64, is64, mid) <= gseg) lo = mid + 1; else hi = mid;
            }
            e = lo;
        }
        const int nrows = e - s;

        // ---- cp.async ring (pair-granular groups) over contiguous [s, e) ----
        const float* base = x + (size_t)s * EMB_DIM + lane * 4;

        #pragma unroll
        for (int d = 0; d < DEPTH_P; d++) {
            const int r0 = 2 * d, r1 = 2 * d + 1;
            if (r0 < nrows) {
                const float* src = base + (size_t)r0 * EMB_DIM;
                asm volatile("cp.async.cg.shared.global [%0], [%1], 16;\n"
                             :: "r"(sbase + r0 * 512), "l"(src));
            }
            if (r1 < nrows) {
                const float* src = base + (size_t)r1 * EMB_DIM;
                asm volatile("cp.async.cg.shared.global [%0], [%1], 16;\n"
                             :: "r"(sbase + r1 * 512), "l"(src));
            }
            asm volatile("cp.async.commit_group;\n");
        }

        float4 acc = make_float4(0.f, 0.f, 0.f, 0.f);
        float  l   = 0.f;
        int slot = 0;   // row slot of current pair (0, 2 or 4)

        const int npairs = nrows >> 1;
        for (int ip = 0; ip < npairs; ip++) {
            asm volatile("cp.async.wait_group %0;\n" :: "n"(DEPTH_P - 1));
            const float4 xv0 = buf[warp][slot][lane];
            const float4 xv1 = buf[warp][slot + 1][lane];

            // refill this pair's slots with rows 2*ip + 2*DEPTH_P (+1)
            const int nr0 = 2 * ip + 2 * DEPTH_P;
            const int nr1 = nr0 + 1;
            if (nr0 < nrows) {
                const float* src = base + (size_t)nr0 * EMB_DIM;
                asm volatile("cp.async.cg.shared.global [%0], [%1], 16;\n"
                             :: "r"(sbase + slot * 512), "l"(src));
            }
            if (nr1 < nrows) {
                const float* src = base + (size_t)nr1 * EMB_DIM;
                asm volatile("cp.async.cg.shared.global [%0], [%1], 16;\n"
                             :: "r"(sbase + (slot + 1) * 512), "l"(src));
            }
            asm volatile("cp.async.commit_group;\n");

            float p0 = xv0.x*wvec.x + xv0.y*wvec.y + xv0.z*wvec.z + xv0.w*wvec.w;
            float p1 = xv1.x*wvec.x + xv1.y*wvec.y + xv1.z*wvec.z + xv1.w*wvec.w;
            #pragma unroll
            for (int o = 16; o; o >>= 1) {
                p0 += __shfl_xor_sync(0xffffffffu, p0, o);
                p1 += __shfl_xor_sync(0xffffffffu, p1, o);
            }
            // no-max softmax (shift-invariant; scores small enough for fp32 exp)
            const float e0 = __expf(p0);
            const float e1 = __expf(p1);
            acc.x += e0*xv0.x; acc.y += e0*xv0.y; acc.z += e0*xv0.z; acc.w += e0*xv0.w;
            acc.x += e1*xv1.x; acc.y += e1*xv1.y; acc.z += e1*xv1.z; acc.w += e1*xv1.w;
            l += e0 + e1;

            slot += 2;
            if (slot == 2 * DEPTH_P) slot = 0;
        }
        if (nrows & 1) {
            asm volatile("cp.async.wait_group 0;\n");
            const float4 xv = buf[warp][slot][lane];
            float p = xv.x*wvec.x + xv.y*wvec.y + xv.z*wvec.z + xv.w*wvec.w;
            #pragma unroll
            for (int o = 16; o; o >>= 1) p += __shfl_xor_sync(0xffffffffu, p, o);
            const float e = __expf(p);
            acc.x += e*xv.x; acc.y += e*xv.y; acc.z += e*xv.z; acc.w += e*xv.w;
            l += e;
        }
        asm volatile("cp.async.wait_group 0;\n");   // drain before slot reuse

        // ---- flush segment into global partials ----
        float* dst = g_acc + (size_t)gseg * EMB_DIM + lane * 4;
        atomicAdd(dst + 0, acc.x);
        atomicAdd(dst + 1, acc.y);
        atomicAdd(dst + 2, acc.z);
        atomicAdd(dst + 3, acc.w);
        if (lane == 0) {
            atomicAdd(&g_l[gseg], l);
            atomicAdd(&g_cnt[gseg], (float)nrows);
        }

        s = e;
        if (s < we) gseg = gid_at(b32, b64, is64, s);
    }
}

// Graph-aligned finalize: block g handles graph g's 128 dims, then restores
// the scratch to zero so the next call starts from a clean state.
__global__ __launch_bounds__(THREADS)
void finalize_kernel(const float* __restrict__ w,
                     float* __restrict__ out, int out_size)
{
    const int g = blockIdx.x;
    const int t = threadIdx.x;
    const int i = g * EMB_DIM + t;

    const float a = g_acc[i];
    const float l = g_l[g];
    const float c = g_cnt[g];
    __syncthreads();                 // all reads of g_l/g_cnt done

    const float denom = fmaxf(l, 1e-30f) * fmaxf(c, 1.0f);
    out[i] = a / denom;

    g_acc[i] = 0.0f;                 // self-clean for the next call
    if (t == 0) { g_l[g] = 0.0f; g_cnt[g] = 0.0f; }

    if (g == 0 && out_size >= NUM_GRAPHS * EMB_DIM + EMB_DIM)
        out[NUM_GRAPHS * EMB_DIM + t] = w[t];
}

extern "C" void kernel_launch(void* const* d_in, const int* in_sizes, int n_in,
                              void* d_out, int out_size)
{
    const float* x     = (const float*)d_in[0];
    const void*  batch = d_in[1];
    const float* w     = (const float*)d_in[2];
    float*       out   = (float*)d_out;
    const int n_nodes  = in_sizes[1];

    att_partial_kernel<<<NBLOCKS, THREADS>>>(x, batch, w, n_nodes);
    finalize_kernel<<<NUM_GRAPHS, THREADS>>>(w, out, out_size);
}

// round 13
// speedup vs baseline: 1.6213x; 1.0211x over previous
#include <cuda_runtime.h>
#include <stdint.h>

#define NUM_GRAPHS 4096
#define EMB_DIM    128
#define THREADS    128
#define DEPTH_P    3                 // cp.async ring depth in PAIRS (6 rows)
#define NBLOCKS    (152 * 16)        // GB300: one exact wave at 16 blocks/SM
#define NWARPS     (NBLOCKS * 4)

// zero-initialized at module load; finalize_kernel restores zeros after use,
// so the invariant holds at the start of every kernel_launch call.
__device__ float g_acc[NUM_GRAPHS * EMB_DIM];
__device__ float g_l[NUM_GRAPHS];
__device__ float g_cnt[NUM_GRAPHS];

__device__ __forceinline__ int gid_at(const int* b32, const long long* b64,
                                      bool is64, int i)
{
    return is64 ? (int)b64[i] : b32[i];
}

__global__ __launch_bounds__(THREADS)
void att_partial_kernel(const float* __restrict__ x,
                        const void* __restrict__ batch_raw,
                        const float* __restrict__ w,
                        int n_nodes)
{
    const int t    = threadIdx.x;
    const int warp = t >> 5;
    const int lane = t & 31;

    __shared__ float4 buf[4][DEPTH_P * 2][32];   // 12 KB ring: [warp][row slot][lane]

    // dtype probe: int32 -> word n-1 is the last graph id (!=0);
    // int64 (values < 2^31, LE) -> word n-1 is an upper half (==0).
    const int*       b32 = (const int*)batch_raw;
    const long long* b64 = (const long long*)batch_raw;
    const bool is64 = (b32[n_nodes - 1] == 0);

    const float4 wvec = ((const float4*)w)[lane];

    // perfectly balanced contiguous warp slice
    const int gw       = blockIdx.x * 4 + warp;
    const int per_warp = (n_nodes + NWARPS - 1) / NWARPS;
    const int ws       = gw * per_warp;
    const int we       = min(n_nodes, ws + per_warp);
    if (ws >= we) return;

    const uint32_t sbase = (uint32_t)__cvta_generic_to_shared(&buf[warp][0][lane]);

    int s = ws;
    int gseg = gid_at(b32, b64, is64, ws);
    const int glast = gid_at(b32, b64, is64, we - 1);

    while (s < we) {
        // segment end: we if this is the slice's last graph, else upper_bound
        int e;
        if (gseg == glast) {
            e = we;
        } else {
            int lo = s + 1, hi = we;
            while (lo < hi) {
                int mid = (lo + hi) >> 1;
                if (gid_at(b32, b64, is64, mid) <= gseg) lo = mid + 1; else hi = mid;
            }
            e = lo;
        }
        const int nrows = e - s;

        // ---- cp.async ring (pair-granular groups) over contiguous [s, e) ----
        const float* base = x + (size_t)s * EMB_DIM + lane * 4;

        #pragma unroll
        for (int d = 0; d < DEPTH_P; d++) {
            const int r0 = 2 * d, r1 = 2 * d + 1;
            if (r0 < nrows) {
                const float* src = base + (size_t)r0 * EMB_DIM;
                asm volatile("cp.async.cg.shared.global [%0], [%1], 16;\n"
                             :: "r"(sbase + r0 * 512), "l"(src));
            }
            if (r1 < nrows) {
                const float* src = base + (size_t)r1 * EMB_DIM;
                asm volatile("cp.async.cg.shared.global [%0], [%1], 16;\n"
                             :: "r"(sbase + r1 * 512), "l"(src));
            }
            asm volatile("cp.async.commit_group;\n");
        }

        float4 acc = make_float4(0.f, 0.f, 0.f, 0.f);
        float  l   = 0.f;
        int slot = 0;   // row slot of current pair (0, 2 or 4)

        const int npairs = nrows >> 1;
        for (int ip = 0; ip < npairs; ip++) {
            asm volatile("cp.async.wait_group %0;\n" :: "n"(DEPTH_P - 1));
            const float4 xv0 = buf[warp][slot][lane];
            const float4 xv1 = buf[warp][slot + 1][lane];

            // refill this pair's slots with rows 2*ip + 2*DEPTH_P (+1)
            const int nr0 = 2 * ip + 2 * DEPTH_P;
            const int nr1 = nr0 + 1;
            if (nr0 < nrows) {
                const float* src = base + (size_t)nr0 * EMB_DIM;
                asm volatile("cp.async.cg.shared.global [%0], [%1], 16;\n"
                             :: "r"(sbase + slot * 512), "l"(src));
            }
            if (nr1 < nrows) {
                const float* src = base + (size_t)nr1 * EMB_DIM;
                asm volatile("cp.async.cg.shared.global [%0], [%1], 16;\n"
                             :: "r"(sbase + (slot + 1) * 512), "l"(src));
            }
            asm volatile("cp.async.commit_group;\n");

            float p0 = xv0.x*wvec.x + xv0.y*wvec.y + xv0.z*wvec.z + xv0.w*wvec.w;
            float p1 = xv1.x*wvec.x + xv1.y*wvec.y + xv1.z*wvec.z + xv1.w*wvec.w;
            #pragma unroll
            for (int o = 16; o; o >>= 1) {
                p0 += __shfl_xor_sync(0xffffffffu, p0, o);
                p1 += __shfl_xor_sync(0xffffffffu, p1, o);
            }
            // no-max softmax (shift-invariant; scores small enough for fp32 exp)
            const float e0 = __expf(p0);
            const float e1 = __expf(p1);
            acc.x += e0*xv0.x; acc.y += e0*xv0.y; acc.z += e0*xv0.z; acc.w += e0*xv0.w;
            acc.x += e1*xv1.x; acc.y += e1*xv1.y; acc.z += e1*xv1.z; acc.w += e1*xv1.w;
            l += e0 + e1;

            slot += 2;
            if (slot == 2 * DEPTH_P) slot = 0;
        }
        if (nrows & 1) {
            asm volatile("cp.async.wait_group 0;\n");
            const float4 xv = buf[warp][slot][lane];
            float p = xv.x*wvec.x + xv.y*wvec.y + xv.z*wvec.z + xv.w*wvec.w;
            #pragma unroll
            for (int o = 16; o; o >>= 1) p += __shfl_xor_sync(0xffffffffu, p, o);
            const float e = __expf(p);
            acc.x += e*xv.x; acc.y += e*xv.y; acc.z += e*xv.z; acc.w += e*xv.w;
            l += e;
        }
        asm volatile("cp.async.wait_group 0;\n");   // drain before slot reuse

        // ---- flush segment into global partials ----
        float* dst = g_acc + (size_t)gseg * EMB_DIM + lane * 4;
        atomicAdd(dst + 0, acc.x);
        atomicAdd(dst + 1, acc.y);
        atomicAdd(dst + 2, acc.z);
        atomicAdd(dst + 3, acc.w);
        if (lane == 0) {
            atomicAdd(&g_l[gseg], l);
            atomicAdd(&g_cnt[gseg], (float)nrows);
        }

        s = e;
        if (s < we) gseg = gid_at(b32, b64, is64, s);
    }
}

// Vectorized finalize: 512 threads/block, one float4 per thread.
// A block covers exactly 16 whole graphs (32 float4 per graph), so the
// read -> sync -> zero sequence on g_l/g_cnt stays block-local.
__global__ __launch_bounds__(512)
void finalize_kernel(const float* __restrict__ w,
                     float* __restrict__ out, int out_size)
{
    const int i = blockIdx.x * 512 + threadIdx.x;   // float4 index, < 131072
    const int g = i >> 5;                           // 32 float4 per graph

    const float4 a = ((const float4*)g_acc)[i];
    const float  l = g_l[g];
    const float  c = g_cnt[g];
    __syncthreads();                                // reads done before zeroing

    const float inv = 1.0f / (fmaxf(l, 1e-30f) * fmaxf(c, 1.0f));
    ((float4*)out)[i] = make_float4(a.x * inv, a.y * inv, a.z * inv, a.w * inv);

    ((float4*)g_acc)[i] = make_float4(0.f, 0.f, 0.f, 0.f);   // self-clean
    if ((i & 31) == 0) { g_l[g] = 0.0f; g_cnt[g] = 0.0f; }

    // second tuple element: att_weight passthrough (32 float4)
    if (blockIdx.x == 0 && threadIdx.x < 32 &&
        out_size >= NUM_GRAPHS * EMB_DIM + EMB_DIM) {
        ((float4*)(out + NUM_GRAPHS * EMB_DIM))[threadIdx.x] =
            ((const float4*)w)[threadIdx.x];
    }
}

extern "C" void kernel_launch(void* const* d_in, const int* in_sizes, int n_in,
                              void* d_out, int out_size)
{
    const float* x     = (const float*)d_in[0];
    const void*  batch = d_in[1];
    const float* w     = (const float*)d_in[2];
    float*       out   = (float*)d_out;
    const int n_nodes  = in_sizes[1];

    att_partial_kernel<<<NBLOCKS, THREADS>>>(x, batch, w, n_nodes);
    finalize_kernel<<<(NUM_GRAPHS * EMB_DIM / 4) / 512, 512>>>(w, out, out_size);
}